// round 1
// baseline (speedup 1.0000x reference)
#include <cuda_runtime.h>
#include <math.h>

// Problem shape (fixed by setup_inputs)
#define BATCH 256
#define TLEN  1024
#define DDIM  256
#define LOG2PI 1.8378770664093453f

// Main-kernel tiling
#define GB      4                 // batches per block
#define NCHUNK  16                // t-chunks
#define CHUNK   (TLEN / NCHUNK)   // 64

// Scratch (no allocations allowed)
__device__ float2 g_tbl[(TLEN - 1) * DDIM];   // (Ad, 1/q) per (t-1, d)   ~2 MB
__device__ float  g_invq0[DDIM];              // 1/var0
__device__ float  g_row[TLEN];                // per-t row sums of log-terms
__device__ float  g_C;                        // total constant

__device__ __forceinline__ float softplusf(float x) {
    // stable for the input range (~ -0.7), guard anyway
    return (x > 20.f) ? x : log1pf(expf(x));
}

// ---------------------------------------------------------------------------
// Kernel 1: precompute tables + per-row log constants; zero the output.
// grid = TLEN blocks, block = DDIM threads
// ---------------------------------------------------------------------------
__global__ void k_precompute(const float* __restrict__ ts,
                             const float* __restrict__ log_kappa,
                             const float* __restrict__ log_sigma,
                             float* __restrict__ out, int out_size) {
    const int t = blockIdx.x;
    const int d = threadIdx.x;

    float kappa = softplusf(log_kappa[d]) + 1e-6f;
    float sigma = softplusf(log_sigma[d]) + 1e-6f;
    float s2 = sigma * sigma;

    float elem;
    if (t == 0) {
        float var0 = fmaxf(s2 / (2.0f * kappa), 1e-10f);
        g_invq0[d] = 1.0f / var0;
        elem = logf(var0) + LOG2PI;
        for (int i = d; i < out_size; i += blockDim.x) out[i] = 0.0f;
    } else {
        float dt = fmaxf(ts[t * DDIM + d] - ts[(t - 1) * DDIM + d], 1e-6f);
        float Ad = expf(-kappa * dt);
        float q  = fmaxf(s2 * (-expm1f(-2.0f * kappa * dt)) / (2.0f * kappa), 1e-10f);
        g_tbl[(t - 1) * DDIM + d] = make_float2(Ad, 1.0f / q);
        elem = logf(q) + LOG2PI;
    }

    // block reduce elem -> g_row[t]
    __shared__ float sm[DDIM];
    sm[d] = elem;
    __syncthreads();
    for (int s = DDIM / 2; s > 0; s >>= 1) {
        if (d < s) sm[d] += sm[d + s];
        __syncthreads();
    }
    if (d == 0) g_row[t] = sm[0];
}

// ---------------------------------------------------------------------------
// Kernel 2: deterministic reduce of g_row -> g_C. 1 block, 256 threads.
// ---------------------------------------------------------------------------
__global__ void k_reduce_c() {
    const int d = threadIdx.x;
    float s = g_row[d] + g_row[d + 256] + g_row[d + 512] + g_row[d + 768];
    __shared__ float sm[256];
    sm[d] = s;
    __syncthreads();
    for (int st = 128; st > 0; st >>= 1) {
        if (d < st) sm[d] += sm[d + st];
        __syncthreads();
    }
    if (d == 0) g_C = sm[0];
}

// ---------------------------------------------------------------------------
// Kernel 3: main streaming pass over y.
// grid = (BATCH/GB) * NCHUNK blocks, block = DDIM threads.
// Each block: GB batches x one CHUNK of the t-axis; table loaded once per t,
// reused across GB batches. Per-batch partial sums atomically added to out.
// ---------------------------------------------------------------------------
__global__ __launch_bounds__(DDIM)
void k_main(const float* __restrict__ y,
            const float* __restrict__ mu,
            float* __restrict__ out) {
    const int c     = blockIdx.x % NCHUNK;
    const int bbase = (blockIdx.x / NCHUNK) * GB;
    const int d     = threadIdx.x;

    const float mu_d = mu[d];

    const float* yb[GB];
#pragma unroll
    for (int g = 0; g < GB; g++)
        yb[g] = y + (size_t)(bbase + g) * (TLEN * DDIM) + d;

    float acc[GB];
    float prev[GB];
#pragma unroll
    for (int g = 0; g < GB; g++) acc[g] = 0.0f;

    const int tstart = c * CHUNK;
    const int t0 = (c == 0) ? 1 : tstart;

#pragma unroll
    for (int g = 0; g < GB; g++) prev[g] = yb[g][(t0 - 1) * DDIM];

    if (c == 0) {
        float iq0 = g_invq0[d];
#pragma unroll
        for (int g = 0; g < GB; g++) {
            float df = prev[g] - mu_d;
            acc[g] += df * df * iq0;
        }
    }

    const int tend = tstart + CHUNK;
    const float2* __restrict__ tbl = g_tbl + d;
#pragma unroll 4
    for (int t = t0; t < tend; ++t) {
        float2 tb = tbl[(t - 1) * DDIM];
#pragma unroll
        for (int g = 0; g < GB; g++) {
            float yv = yb[g][t * DDIM];
            float df = (yv - mu_d) - tb.x * (prev[g] - mu_d);
            acc[g] += df * df * tb.y;
            prev[g] = yv;
        }
    }

    // Reduce: warp shuffle, then cross-warp in smem.
    const int lane = d & 31;
    const int warp = d >> 5;
    __shared__ float sm[(DDIM / 32) * GB];
#pragma unroll
    for (int g = 0; g < GB; g++) {
        float v = acc[g];
#pragma unroll
        for (int o = 16; o > 0; o >>= 1) v += __shfl_down_sync(0xffffffffu, v, o);
        if (lane == 0) sm[warp * GB + g] = v;
    }
    __syncthreads();
    if (d < GB) {
        float s = 0.0f;
#pragma unroll
        for (int w = 0; w < DDIM / 32; w++) s += sm[w * GB + d];
        atomicAdd(&out[bbase + d], -0.5f * s);
    }
}

// ---------------------------------------------------------------------------
// Kernel 4: add the batch-independent constant.
// ---------------------------------------------------------------------------
__global__ void k_finalize(float* __restrict__ out, int out_size) {
    int i = threadIdx.x;
    if (i < out_size) out[i] -= 0.5f * g_C;
}

extern "C" void kernel_launch(void* const* d_in, const int* in_sizes, int n_in,
                              void* d_out, int out_size) {
    const float* y  = (const float*)d_in[0];
    const float* ts = (const float*)d_in[1];
    const float* mu = (const float*)d_in[2];
    const float* lk = (const float*)d_in[3];
    const float* ls = (const float*)d_in[4];
    float* out = (float*)d_out;

    k_precompute<<<TLEN, DDIM>>>(ts, lk, ls, out, out_size);
    k_reduce_c<<<1, 256>>>();
    k_main<<<(BATCH / GB) * NCHUNK, DDIM>>>(y, mu, out);
    k_finalize<<<1, 256>>>(out, out_size);
}